// round 3
// baseline (speedup 1.0000x reference)
#include <cuda_runtime.h>
#include <math.h>
#include <stdint.h>

// Problem constants (fixed by the reference)
#define HD    128
#define HQ    32
#define HKV   8
#define SEQ   4096
#define BQ    128
#define BKV   128
#define WIN   512
#define CAPV  50.0f
#define EPSV  1e-5f
#define SCL   0.08838834764831845f   // 1/sqrt(128)

// Shared memory strides (floats)
#define QT_STRIDE 68    // QsT: [128 d][64 i + pad]
#define KT_STRIDE 132   // KsT: [128 d][128 j + pad]
#define VS_STRIDE 132   // Vs : [128 j][128 d + pad]
#define PS_STRIDE 132   // Ps : [64 i][128 j + pad]

#define BUFA_FLOATS 8704    // max(128*68, 64*132)
#define BUFB_FLOATS 16896   // 128*132
#define SMEM_FLOATS (BUFA_FLOATS + BUFB_FLOATS + 128)

#define ROWS_PER_CHUNK 8
#define N_PRE 2            // copy chunks a deferred compute CTA does before computing

__device__ int g_chunk_counter;

__global__ void init_counter_kernel() { g_chunk_counter = 0; }

typedef unsigned long long u64;

__device__ __forceinline__ void fma2(u64& acc, u64 a, u64 b) {
    asm("fma.rn.f32x2 %0, %1, %2, %0;" : "+l"(acc) : "l"(a), "l"(b));
}
__device__ __forceinline__ u64 pack2(float x, float y) {
    u64 r; asm("mov.b64 %0, {%1, %2};" : "=l"(r) : "f"(x), "f"(y)); return r;
}
__device__ __forceinline__ float2 unpack2(u64 p) {
    float2 r; asm("mov.b64 {%0, %1}, %2;" : "=f"(r.x), "=f"(r.y) : "l"(p)); return r;
}

__device__ __forceinline__ float warpSum(float v) {
    #pragma unroll
    for (int o = 16; o; o >>= 1) v += __shfl_xor_sync(0xffffffffu, v, o);
    return v;
}
__device__ __forceinline__ float warpMax(float v) {
    #pragma unroll
    for (int o = 16; o; o >>= 1) v = fmaxf(v, __shfl_xor_sync(0xffffffffu, v, o));
    return v;
}

struct CopyCtx {
    const float4* src_o;
    float4*       dst_o;
    const float4* src_l;
    float4*       dst_l;
    int row0;
    int nChunkO;
};

// Copy one chunk c. Chunks < nChunkO are 8 full global_o rows (128KB);
// the rest are one (batch,head) lse row each, skipping the updated slice.
__device__ __forceinline__ void copy_chunk(const CopyCtx& cc, int c, int t)
{
    const int SROWS = SEQ - BQ;   // 3968
    if (c < cc.nChunkO) {
        const int vr0 = c * ROWS_PER_CHUNK;
        #pragma unroll
        for (int rr = 0; rr < ROWS_PER_CHUNK; rr += 2) {
            const int vrA = vr0 + rr, vrB = vr0 + rr + 1;
            const int bA = vrA / SROWS, bB = vrB / SROWS;
            const int sA0 = vrA - bA * SROWS, sB0 = vrB - bB * SROWS;
            const int sA = sA0 + (sA0 >= cc.row0 ? BQ : 0);
            const int sB = sB0 + (sB0 >= cc.row0 ? BQ : 0);
            const size_t rbA = (((size_t)bA * SEQ + sA) * HQ * HD) >> 2;
            const size_t rbB = (((size_t)bB * SEQ + sB) * HQ * HD) >> 2;
            float4 tmp[8];
            #pragma unroll
            for (int u = 0; u < 4; u++) tmp[u]     = __ldcs(cc.src_o + rbA + t + u * 256);
            #pragma unroll
            for (int u = 0; u < 4; u++) tmp[4 + u] = __ldcs(cc.src_o + rbB + t + u * 256);
            #pragma unroll
            for (int u = 0; u < 4; u++) __stcs(cc.dst_o + rbA + t + u * 256, tmp[u]);
            #pragma unroll
            for (int u = 0; u < 4; u++) __stcs(cc.dst_o + rbB + t + u * 256, tmp[4 + u]);
        }
    } else {
        const int hb = c - cc.nChunkO;              // 0 .. B*HQ-1
        const size_t base = (size_t)hb * SEQ;
        const int npos4 = SROWS >> 2;               // 992
        for (int p4 = t; p4 < npos4; p4 += 256) {
            const int p = p4 * 4;
            const int s = p + (p >= cc.row0 ? BQ : 0); // row0 % 4 == 0 -> stays aligned
            __stcs(cc.dst_l + ((base + s) >> 2), __ldcs(cc.src_l + ((base + s) >> 2)));
        }
    }
}

__global__ __launch_bounds__(256, 2)
void oswa_fused_kernel(
    const float* __restrict__ q,   const float* __restrict__ k,
    const float* __restrict__ v,   const float* __restrict__ go,
    const float* __restrict__ glse,
    const float* __restrict__ gq,  const float* __restrict__ gk,
    const int* __restrict__ biq,   const int* __restrict__ bikv,
    float* __restrict__ out,
    int B, int nComputeBlocks, int nChunkO, int nChunkTotal)
{
    extern __shared__ float sm[];
    float* bufA = sm;                       // QsT then Ps
    float* bufB = sm + BUFA_FLOATS;         // KsT then Vs
    float* smax = sm + BUFA_FLOATS + BUFB_FLOATS;   // [64]
    float* slse = smax + 64;                        // [64]
    __shared__ int s_chunk;

    const int t    = threadIdx.x;
    const int lane = t & 31;
    const int w    = t >> 5;

    const int bidq  = biq[0];
    const int bidkv = bikv[0];
    const int row0  = bidq * BQ;
    const size_t O_ELEMS = (size_t)B * SEQ * HQ * HD;

    CopyCtx cc;
    cc.src_o = (const float4*)go;
    cc.dst_o = (float4*)out;
    cc.src_l = (const float4*)glse;
    cc.dst_l = (float4*)(out + O_ELEMS);
    cc.row0  = row0;
    cc.nChunkO = nChunkO;

    const int bid = blockIdx.x;

    if (bid < nComputeBlocks) {
        // ---- stagger: the second co-resident CTA on each SM (bid>=148) copies
        //      N_PRE chunks first so DRAM stays fed while its partner computes.
        if (bid >= 148) {
            for (int it = 0; it < N_PRE; it++) {
                if (t == 0) s_chunk = atomicAdd(&g_chunk_counter, 1);
                __syncthreads();
                const int c = s_chunk;
                __syncthreads();
                if (c < nChunkTotal) copy_chunk(cc, c, t);
                else break;
            }
        }

        // ---------------- attention tile: (batch, head, q-half of 64 rows) ----------------
        const int half  = bid & 1;
        const int h     = (bid >> 1) % HQ;
        const int batch = bid / (2 * HQ);
        const int kh    = h / (HQ / HKV);

        // ---- load+RMSNorm K -> KsT[d][j]  (warp w handles rows w*16 .. w*16+15) ----
        {
            const float4 g4 = *(const float4*)(gk + kh * HD + lane * 4);
            const float gv[4] = {g4.x, g4.y, g4.z, g4.w};
            #pragma unroll 4
            for (int jj = 0; jj < 16; jj++) {
                const int j = w * 16 + jj;
                const float4 kv4 = *(const float4*)(k + (((size_t)batch * BKV + j) * HKV + kh) * HD + lane * 4);
                float ss = kv4.x * kv4.x + kv4.y * kv4.y + kv4.z * kv4.z + kv4.w * kv4.w;
                ss = warpSum(ss);
                const float rstd = rsqrtf(ss * (1.0f / HD) + EPSV);
                const float kv[4] = {kv4.x, kv4.y, kv4.z, kv4.w};
                #pragma unroll
                for (int e = 0; e < 4; e++) {
                    const int jr = (e + lane) & 3;           // rotate to reduce STS conflicts
                    const int d  = lane * 4 + jr;
                    bufB[d * KT_STRIDE + j] = kv[jr] * rstd * gv[jr];
                }
            }
        }
        // ---- load+RMSNorm Q -> QsT[d][i]  (warp w handles local rows w*8 .. w*8+7) ----
        {
            const float4 g4 = *(const float4*)(gq + h * HD + lane * 4);
            const float gv[4] = {g4.x, g4.y, g4.z, g4.w};
            #pragma unroll 4
            for (int ii = 0; ii < 8; ii++) {
                const int i    = w * 8 + ii;
                const int qrow = half * 64 + i;
                const float4 qv4 = *(const float4*)(q + (((size_t)batch * BQ + qrow) * HQ + h) * HD + lane * 4);
                float ss = qv4.x * qv4.x + qv4.y * qv4.y + qv4.z * qv4.z + qv4.w * qv4.w;
                ss = warpSum(ss);
                const float rstd = rsqrtf(ss * (1.0f / HD) + EPSV);
                const float qv[4] = {qv4.x, qv4.y, qv4.z, qv4.w};
                #pragma unroll
                for (int e = 0; e < 4; e++) {
                    const int jr = (e + lane) & 3;
                    const int d  = lane * 4 + jr;
                    bufA[d * QT_STRIDE + i] = qv[jr] * rstd * gv[jr];
                }
            }
        }
        __syncthreads();

        // ---- GEMM1: S[64][128] = QsT^T * KsT  (thread: 4 rows x 8 cols, f32x2) ----
        const int i0 = (t >> 4) * 4;       // 0..60
        const int c0 = (t & 15) * 8;       // 0..120
        u64 accp[4][4];
        #pragma unroll
        for (int r = 0; r < 4; r++)
            #pragma unroll
            for (int c = 0; c < 4; c++) accp[r][c] = 0ull;

        #pragma unroll 4
        for (int d = 0; d < HD; d++) {
            const float4 a4 = *(const float4*)&bufA[d * QT_STRIDE + i0];
            const ulonglong2 bq0 = *(const ulonglong2*)&bufB[d * KT_STRIDE + c0];
            const ulonglong2 bq1 = *(const ulonglong2*)&bufB[d * KT_STRIDE + c0 + 4];
            const u64 bp[4] = {bq0.x, bq0.y, bq1.x, bq1.y};
            const u64 ap[4] = {pack2(a4.x, a4.x), pack2(a4.y, a4.y),
                               pack2(a4.z, a4.z), pack2(a4.w, a4.w)};
            #pragma unroll
            for (int r = 0; r < 4; r++)
                #pragma unroll
                for (int c = 0; c < 4; c++) fma2(accp[r][c], ap[r], bp[c]);
        }
        __syncthreads();   // all done reading bufA/bufB

        // ---- cap + mask -> Ps (bufA) ; cooperative V load -> Vs (bufB) ----
        #pragma unroll
        for (int r = 0; r < 4; r++) {
            const int qi = row0 + half * 64 + i0 + r;
            #pragma unroll
            for (int cp = 0; cp < 4; cp++) {
                const float2 av = unpack2(accp[r][cp]);
                const float vv[2] = {av.x, av.y};
                #pragma unroll
                for (int e = 0; e < 2; e++) {
                    const int c = cp * 2 + e;
                    const int kj = bidkv * BKV + c0 + c;
                    const float lg = CAPV * tanhf(vv[e] * (SCL / CAPV));
                    const bool allowed = (kj <= qi) && (kj >= qi - WIN) && (qi < SEQ) && (kj < SEQ);
                    bufA[(i0 + r) * PS_STRIDE + c0 + c] = allowed ? lg : -INFINITY;
                }
            }
        }
        #pragma unroll 4
        for (int idx = t; idx < BKV * (HD / 4); idx += 256) {
            const int j  = idx >> 5;
            const int c4 = idx & 31;
            const float4 vv = *(const float4*)(v + (((size_t)batch * BKV + j) * HKV + kh) * HD + c4 * 4);
            *(float4*)&bufB[j * VS_STRIDE + c4 * 4] = vv;
        }
        __syncthreads();

        // ---- row softmax (warp w handles rows w*8 .. w*8+7) ----
        #pragma unroll
        for (int rr = 0; rr < 8; rr++) {
            const int row = w * 8 + rr;
            float x0 = bufA[row * PS_STRIDE + lane];
            float x1 = bufA[row * PS_STRIDE + lane + 32];
            float x2 = bufA[row * PS_STRIDE + lane + 64];
            float x3 = bufA[row * PS_STRIDE + lane + 96];
            float m = warpMax(fmaxf(fmaxf(x0, x1), fmaxf(x2, x3)));
            float e0, e1, e2, e3;
            if (m == -INFINITY) { e0 = e1 = e2 = e3 = 0.0f; }
            else {
                e0 = expf(x0 - m); e1 = expf(x1 - m);
                e2 = expf(x2 - m); e3 = expf(x3 - m);
            }
            const float ssum = warpSum(e0 + e1 + e2 + e3);
            bufA[row * PS_STRIDE + lane]      = e0;
            bufA[row * PS_STRIDE + lane + 32] = e1;
            bufA[row * PS_STRIDE + lane + 64] = e2;
            bufA[row * PS_STRIDE + lane + 96] = e3;
            if (lane == 0) {
                smax[row] = m;
                slse[row] = (ssum > 0.0f) ? (m + logf(ssum)) : -INFINITY;
            }
        }
        __syncthreads();

        // ---- GEMM2: Ounnorm[64][128] = Ps * Vs  (thread: 4 rows x 8 d-cols, f32x2) ----
        u64 acc2p[4][4];
        #pragma unroll
        for (int r = 0; r < 4; r++)
            #pragma unroll
            for (int c = 0; c < 4; c++) acc2p[r][c] = 0ull;

        #pragma unroll 4
        for (int j = 0; j < BKV; j++) {
            const ulonglong2 bq0 = *(const ulonglong2*)&bufB[j * VS_STRIDE + c0];
            const ulonglong2 bq1 = *(const ulonglong2*)&bufB[j * VS_STRIDE + c0 + 4];
            const u64 bp[4] = {bq0.x, bq0.y, bq1.x, bq1.y};
            u64 ap[4];
            #pragma unroll
            for (int r = 0; r < 4; r++) {
                const float a = bufA[(i0 + r) * PS_STRIDE + j];
                ap[r] = pack2(a, a);
            }
            #pragma unroll
            for (int r = 0; r < 4; r++)
                #pragma unroll
                for (int c = 0; c < 4; c++) fma2(acc2p[r][c], ap[r], bp[c]);
        }

        // ---- online merge + writeout ----
        #pragma unroll
        for (int r = 0; r < 4; r++) {
            const int row = i0 + r;
            const int s   = row0 + half * 64 + row;
            const float lse_old = glse[((size_t)batch * HQ + h) * SEQ + s];
            const float m  = smax[row];
            const float lb = slse[row];
            const float mx = fmaxf(lse_old, lb);
            const float lse_new = (mx == -INFINITY) ? -INFINITY
                                 : mx + log1pf(expf(fminf(lse_old, lb) - mx));
            const bool fin = isfinite(lse_new);
            const float c_old = fin ? expf(lse_old - lse_new) : 0.0f;
            const float cb    = fin ? expf(m - lse_new) : 0.0f;   // absorbs 1/sum

            const float2 a0 = unpack2(acc2p[r][0]);
            const float2 a1 = unpack2(acc2p[r][1]);
            const float2 a2 = unpack2(acc2p[r][2]);
            const float2 a3 = unpack2(acc2p[r][3]);

            const size_t base = (((size_t)batch * SEQ + s) * HQ + h) * HD + c0;
            const float4 o0 = *(const float4*)(go + base);
            const float4 o1 = *(const float4*)(go + base + 4);
            float4 w0, w1;
            w0.x = c_old * o0.x + cb * a0.x;
            w0.y = c_old * o0.y + cb * a0.y;
            w0.z = c_old * o0.z + cb * a1.x;
            w0.w = c_old * o0.w + cb * a1.y;
            w1.x = c_old * o1.x + cb * a2.x;
            w1.y = c_old * o1.y + cb * a2.y;
            w1.z = c_old * o1.z + cb * a3.x;
            w1.w = c_old * o1.w + cb * a3.y;
            *(float4*)(out + base)     = w0;
            *(float4*)(out + base + 4) = w1;

            if ((t & 15) == 0)
                out[O_ELEMS + ((size_t)batch * HQ + h) * SEQ + s] = lse_new;
        }
    }

    // ---------------- dynamic copy of the remaining output regions ----------------
    while (true) {
        if (t == 0) s_chunk = atomicAdd(&g_chunk_counter, 1);
        __syncthreads();
        const int c = s_chunk;
        __syncthreads();
        if (c >= nChunkTotal) break;
        copy_chunk(cc, c, t);
    }
}

extern "C" void kernel_launch(void* const* d_in, const int* in_sizes, int n_in,
                              void* d_out, int out_size)
{
    const float* q    = (const float*)d_in[0];
    const float* k    = (const float*)d_in[1];
    const float* v    = (const float*)d_in[2];
    const float* go   = (const float*)d_in[3];
    const float* glse = (const float*)d_in[4];
    const float* gq   = (const float*)d_in[5];
    const float* gk   = (const float*)d_in[6];
    const int*   biq  = (const int*)d_in[7];
    const int*   bikv = (const int*)d_in[8];
    float* out = (float*)d_out;

    const int B = in_sizes[0] / (BQ * HQ * HD);           // 4
    const int nCompute    = B * HQ * 2;                   // 256
    const int nChunkO     = (B * (SEQ - BQ)) / ROWS_PER_CHUNK; // 1984
    const int nChunkTotal = nChunkO + B * HQ;             // +128 lse chunks

    const size_t smem = SMEM_FLOATS * sizeof(float);      // ~100.5 KB
    cudaFuncSetAttribute(oswa_fused_kernel,
                         cudaFuncAttributeMaxDynamicSharedMemorySize, (int)smem);

    const int grid = nCompute + 40;   // 296 = 2 CTAs/SM * 148 SMs (fill with pure-copy CTAs)

    init_counter_kernel<<<1, 1>>>();
    oswa_fused_kernel<<<grid, 256, smem>>>(q, k, v, go, glse, gq, gk, biq, bikv,
                                           out, B, nCompute, nChunkO, nChunkTotal);
}

// round 4
// speedup vs baseline: 1.4127x; 1.4127x over previous
#include <cuda_runtime.h>
#include <math.h>
#include <stdint.h>

// Problem constants (fixed by the reference)
#define HD    128
#define HQ    32
#define HKV   8
#define SEQ   4096
#define BQ    128
#define BKV   128
#define WIN   512
#define CAPV  50.0f
#define EPSV  1e-5f
#define SCL   0.08838834764831845f   // 1/sqrt(128)

#define ROWS_PER_CHUNK 8
#define N_PRE 1

// ---- shared memory layout (32-bit words) ----
// Ks2: [64 kpair][128 j]  bf16x2 packed along d     (8192 w)
// Vs2: [64 jpair][128 d]  bf16x2 packed along j     (8192 w)
// Qs2: [64 kpair][64 i]   bf16x2 packed along d     (4096 w)  -- aliased by Ps2
// scalars: partM[2][64], partS[2][64], sOld[64], sCb[64]
#define KS2_OFF   0
#define VS2_OFF   8192
#define QS2_OFF   16384
#define PS2_OFF   16384
#define PARTM_OFF 20480
#define PARTS_OFF 20608
#define SOLD_OFF  20736
#define SCB_OFF   20800
#define SMEM_WORDS 20880

__device__ int g_chunk_counter;
__global__ void init_counter_kernel() { g_chunk_counter = 0; }

__device__ __forceinline__ int kv_idx(int kp, int col) {   // stride-128 arrays
    return kp * 128 + (col ^ ((kp & 3) << 3));
}
__device__ __forceinline__ int qp_idx(int kp, int col) {   // stride-64 arrays
    return kp * 64 + (col ^ ((kp & 3) << 3));
}

__device__ __forceinline__ uint32_t pack_bf16x2(float lo, float hi) {
    uint32_t r;
    asm("cvt.rn.bf16x2.f32 %0, %1, %2;" : "=r"(r) : "f"(hi), "f"(lo));
    return r;
}

__device__ __forceinline__ void mma16816(float* c,
    uint32_t a0, uint32_t a1, uint32_t a2, uint32_t a3,
    uint32_t b0, uint32_t b1)
{
    asm volatile(
        "mma.sync.aligned.m16n8k16.row.col.f32.bf16.bf16.f32 "
        "{%0,%1,%2,%3}, {%4,%5,%6,%7}, {%8,%9}, {%0,%1,%2,%3};"
        : "+f"(c[0]), "+f"(c[1]), "+f"(c[2]), "+f"(c[3])
        : "r"(a0), "r"(a1), "r"(a2), "r"(a3), "r"(b0), "r"(b1));
}

struct CopyCtx {
    const float4* src_o;
    float4*       dst_o;
    const float4* src_l;
    float4*       dst_l;
    int row0;
    int nChunkO;
};

__device__ __forceinline__ void copy_chunk(const CopyCtx& cc, int c, int t)
{
    const int SROWS = SEQ - BQ;   // 3968
    if (c < cc.nChunkO) {
        const int vr0 = c * ROWS_PER_CHUNK;
        #pragma unroll
        for (int rr = 0; rr < ROWS_PER_CHUNK; rr += 2) {
            const int vrA = vr0 + rr, vrB = vr0 + rr + 1;
            const int bA = vrA / SROWS, bB = vrB / SROWS;
            const int sA0 = vrA - bA * SROWS, sB0 = vrB - bB * SROWS;
            const int sA = sA0 + (sA0 >= cc.row0 ? BQ : 0);
            const int sB = sB0 + (sB0 >= cc.row0 ? BQ : 0);
            const size_t rbA = (((size_t)bA * SEQ + sA) * HQ * HD) >> 2;
            const size_t rbB = (((size_t)bB * SEQ + sB) * HQ * HD) >> 2;
            float4 tmp[8];
            #pragma unroll
            for (int u = 0; u < 4; u++) tmp[u]     = __ldcs(cc.src_o + rbA + t + u * 256);
            #pragma unroll
            for (int u = 0; u < 4; u++) tmp[4 + u] = __ldcs(cc.src_o + rbB + t + u * 256);
            #pragma unroll
            for (int u = 0; u < 4; u++) __stcs(cc.dst_o + rbA + t + u * 256, tmp[u]);
            #pragma unroll
            for (int u = 0; u < 4; u++) __stcs(cc.dst_o + rbB + t + u * 256, tmp[4 + u]);
        }
    } else {
        const int hb = c - cc.nChunkO;
        const size_t base = (size_t)hb * SEQ;
        const int npos4 = SROWS >> 2;   // 992
        for (int p4 = t; p4 < npos4; p4 += 256) {
            const int p = p4 * 4;
            const int s = p + (p >= cc.row0 ? BQ : 0);
            __stcs(cc.dst_l + ((base + s) >> 2), __ldcs(cc.src_l + ((base + s) >> 2)));
        }
    }
}

__global__ __launch_bounds__(256, 2)
void oswa_fused_kernel(
    const float* __restrict__ q,   const float* __restrict__ k,
    const float* __restrict__ v,   const float* __restrict__ go,
    const float* __restrict__ glse,
    const float* __restrict__ gq,  const float* __restrict__ gk,
    const int* __restrict__ biq,   const int* __restrict__ bikv,
    float* __restrict__ out,
    int B, int nComputeBlocks, int nChunkO, int nChunkTotal)
{
    extern __shared__ uint32_t smw[];
    float* smf = (float*)smw;
    __shared__ int s_chunk;

    const int t    = threadIdx.x;
    const int lane = t & 31;
    const int w    = t >> 5;

    const int bidq  = biq[0];
    const int bidkv = bikv[0];
    const int row0  = bidq * BQ;
    const size_t O_ELEMS = (size_t)B * SEQ * HQ * HD;

    CopyCtx cc;
    cc.src_o = (const float4*)go;
    cc.dst_o = (float4*)out;
    cc.src_l = (const float4*)glse;
    cc.dst_l = (float4*)(out + O_ELEMS);
    cc.row0  = row0;
    cc.nChunkO = nChunkO;

    const int bid = blockIdx.x;

    if (bid < nComputeBlocks) {
        if (bid >= 148) {
            // stagger: second co-resident CTA copies one chunk first
            for (int it = 0; it < N_PRE; it++) {
                if (t == 0) s_chunk = atomicAdd(&g_chunk_counter, 1);
                __syncthreads();
                const int c = s_chunk;
                __syncthreads();
                if (c < nChunkTotal) copy_chunk(cc, c, t);
                else break;
            }
        }

        // ---------------- attention tile: (batch, head, q-half of 64 rows) ----------------
        const int half  = bid & 1;
        const int h     = (bid >> 1) % HQ;
        const int batch = bid / (2 * HQ);
        const int kh    = h / (HQ / HKV);

        const int r4 = lane & 3;      // row-offset within 4-row group (loaders)
        const int qd = lane >> 2;     // d-group (loaders)

        // ---- K: load + RMSNorm + pack -> Ks2[kpair][j]  (4 rows/warp/iter, 4 iters) ----
        {
            #pragma unroll
            for (int it = 0; it < 4; it++) {
                const int j = it * 32 + w * 4 + r4;
                const float* kr = k + (((size_t)batch * BKV + j) * HKV + kh) * HD;
                float2 xv[8];
                float ss = 0.0f;
                #pragma unroll
                for (int p = 0; p < 8; p++) {
                    xv[p] = *(const float2*)(kr + 2 * qd + 16 * p);
                    ss += xv[p].x * xv[p].x + xv[p].y * xv[p].y;
                }
                ss += __shfl_xor_sync(0xffffffffu, ss, 4);
                ss += __shfl_xor_sync(0xffffffffu, ss, 8);
                ss += __shfl_xor_sync(0xffffffffu, ss, 16);
                const float rstd = rsqrtf(ss * (1.0f / HD) + EPSV);
                #pragma unroll
                for (int p = 0; p < 8; p++) {
                    const float2 g2 = *(const float2*)(gk + kh * HD + 2 * qd + 16 * p);
                    const int kp = qd + 8 * p;
                    smw[KS2_OFF + kv_idx(kp, j)] =
                        pack_bf16x2(xv[p].x * rstd * g2.x, xv[p].y * rstd * g2.y);
                }
            }
        }
        // ---- Q: load + RMSNorm + pack -> Qs2[kpair][i]  (2 iters) ----
        {
            #pragma unroll
            for (int it = 0; it < 2; it++) {
                const int i = it * 32 + w * 4 + r4;
                const int qrow = half * 64 + i;
                const float* qr = q + (((size_t)batch * BQ + qrow) * HQ + h) * HD;
                float2 xv[8];
                float ss = 0.0f;
                #pragma unroll
                for (int p = 0; p < 8; p++) {
                    xv[p] = *(const float2*)(qr + 2 * qd + 16 * p);
                    ss += xv[p].x * xv[p].x + xv[p].y * xv[p].y;
                }
                ss += __shfl_xor_sync(0xffffffffu, ss, 4);
                ss += __shfl_xor_sync(0xffffffffu, ss, 8);
                ss += __shfl_xor_sync(0xffffffffu, ss, 16);
                const float rstd = rsqrtf(ss * (1.0f / HD) + EPSV);
                #pragma unroll
                for (int p = 0; p < 8; p++) {
                    const float2 g2 = *(const float2*)(gq + h * HD + 2 * qd + 16 * p);
                    const int kp = qd + 8 * p;
                    smw[QS2_OFF + qp_idx(kp, i)] =
                        pack_bf16x2(xv[p].x * rstd * g2.x, xv[p].y * rstd * g2.y);
                }
            }
        }
        // ---- V: load + pack pairs along j -> Vs2[jpair][d]  (2 iters) ----
        {
            #pragma unroll
            for (int it = 0; it < 2; it++) {
                const int jp = it * 32 + w * 4 + r4;
                const float* v0 = v + (((size_t)batch * BKV + 2 * jp) * HKV + kh) * HD;
                const float* v1 = v0 + (size_t)HKV * HD;
                #pragma unroll
                for (int p = 0; p < 8; p++) {
                    const int d0 = 2 * qd + 16 * p;
                    const float2 f0 = *(const float2*)(v0 + d0);
                    const float2 f1 = *(const float2*)(v1 + d0);
                    const int idx = VS2_OFF + kv_idx(jp, d0);   // d0 even -> idx,idx+1 contiguous
                    uint2 wv;
                    wv.x = pack_bf16x2(f0.x, f1.x);
                    wv.y = pack_bf16x2(f0.y, f1.y);
                    *(uint2*)(smw + idx) = wv;
                }
            }
        }
        __syncthreads();

        // ---- GEMM1: S[64][128] = Qn * Kn^T via mma.m16n8k16 ----
        const int g   = lane >> 2;     // 0..7
        const int tg  = lane & 3;      // 0..3
        const int wm  = w & 3;
        const int wn  = w >> 2;
        const int m0  = wm * 16;
        const int nbase = wn * 64;

        float acc[8][4];
        #pragma unroll
        for (int nb = 0; nb < 8; nb++)
            #pragma unroll
            for (int c = 0; c < 4; c++) acc[nb][c] = 0.0f;

        #pragma unroll
        for (int ks = 0; ks < 8; ks++) {
            const int kb = ks * 8;
            const uint32_t a0 = smw[QS2_OFF + qp_idx(kb + tg,     m0 + g)];
            const uint32_t a1 = smw[QS2_OFF + qp_idx(kb + tg,     m0 + g + 8)];
            const uint32_t a2 = smw[QS2_OFF + qp_idx(kb + tg + 4, m0 + g)];
            const uint32_t a3 = smw[QS2_OFF + qp_idx(kb + tg + 4, m0 + g + 8)];
            #pragma unroll
            for (int nb = 0; nb < 8; nb++) {
                const uint32_t b0 = smw[KS2_OFF + kv_idx(kb + tg,     nbase + nb * 8 + g)];
                const uint32_t b1 = smw[KS2_OFF + kv_idx(kb + tg + 4, nbase + nb * 8 + g)];
                mma16816(acc[nb], a0, a1, a2, a3, b0, b1);
            }
        }

        // ---- cap + mask in-frag ----
        const int mA = m0 + g, mB = m0 + g + 8;
        const int qiA = row0 + half * 64 + mA;
        const int qiB = row0 + half * 64 + mB;
        #pragma unroll
        for (int nb = 0; nb < 8; nb++) {
            #pragma unroll
            for (int c = 0; c < 4; c++) {
                const int n_ = nbase + nb * 8 + 2 * tg + (c & 1);
                const int kj = bidkv * BKV + n_;
                const int qi = (c < 2) ? qiA : qiB;
                const float lg = CAPV * tanhf(acc[nb][c] * (SCL / CAPV));
                const bool allowed = (kj <= qi) && (kj >= qi - WIN) && (qi < SEQ) && (kj < SEQ);
                acc[nb][c] = allowed ? lg : -INFINITY;
            }
        }

        // ---- softmax: per-row max (tg-shfl + 2-warp smem combine) ----
        float pmA = -INFINITY, pmB = -INFINITY;
        #pragma unroll
        for (int nb = 0; nb < 8; nb++) {
            pmA = fmaxf(pmA, fmaxf(acc[nb][0], acc[nb][1]));
            pmB = fmaxf(pmB, fmaxf(acc[nb][2], acc[nb][3]));
        }
        pmA = fmaxf(pmA, __shfl_xor_sync(0xffffffffu, pmA, 1));
        pmA = fmaxf(pmA, __shfl_xor_sync(0xffffffffu, pmA, 2));
        pmB = fmaxf(pmB, __shfl_xor_sync(0xffffffffu, pmB, 1));
        pmB = fmaxf(pmB, __shfl_xor_sync(0xffffffffu, pmB, 2));
        if (tg == 0) {
            smf[PARTM_OFF + wn * 64 + mA] = pmA;
            smf[PARTM_OFF + wn * 64 + mB] = pmB;
        }
        __syncthreads();
        const float rowMA = fmaxf(smf[PARTM_OFF + mA], smf[PARTM_OFF + 64 + mA]);
        const float rowMB = fmaxf(smf[PARTM_OFF + mB], smf[PARTM_OFF + 64 + mB]);

        // ---- e = exp(x - rowmax), partial sums, write P (bf16x2) into Ps2 ----
        float psA = 0.0f, psB = 0.0f;
        #pragma unroll
        for (int nb = 0; nb < 8; nb++) {
            float e0 = (rowMA == -INFINITY) ? 0.0f : expf(acc[nb][0] - rowMA);
            float e1 = (rowMA == -INFINITY) ? 0.0f : expf(acc[nb][1] - rowMA);
            float e2 = (rowMB == -INFINITY) ? 0.0f : expf(acc[nb][2] - rowMB);
            float e3 = (rowMB == -INFINITY) ? 0.0f : expf(acc[nb][3] - rowMB);
            psA += e0 + e1;
            psB += e2 + e3;
            const int kp = (nbase >> 1) + nb * 4 + tg;
            smw[PS2_OFF + qp_idx(kp, mA)] = pack_bf16x2(e0, e1);
            smw[PS2_OFF + qp_idx(kp, mB)] = pack_bf16x2(e2, e3);
        }
        psA += __shfl_xor_sync(0xffffffffu, psA, 1);
        psA += __shfl_xor_sync(0xffffffffu, psA, 2);
        psB += __shfl_xor_sync(0xffffffffu, psB, 1);
        psB += __shfl_xor_sync(0xffffffffu, psB, 2);
        if (tg == 0) {
            smf[PARTS_OFF + wn * 64 + mA] = psA;
            smf[PARTS_OFF + wn * 64 + mB] = psB;
        }
        __syncthreads();

        // ---- per-row merge scalars (one thread per row) ----
        if (tg == 0 && wn == 0) {
            #pragma unroll
            for (int rsel = 0; rsel < 2; rsel++) {
                const int m_  = rsel ? mB : mA;
                const float rowM = rsel ? rowMB : rowMA;
                const float ssum = smf[PARTS_OFF + m_] + smf[PARTS_OFF + 64 + m_];
                const float lb = (ssum > 0.0f) ? (rowM + logf(ssum)) : -INFINITY;
                const int s = row0 + half * 64 + m_;
                const float lse_old = glse[((size_t)batch * HQ + h) * SEQ + s];
                const float mx = fmaxf(lse_old, lb);
                const float lse_new = (mx == -INFINITY) ? -INFINITY
                                     : mx + log1pf(expf(fminf(lse_old, lb) - mx));
                const bool fin = isfinite(lse_new);
                smf[SOLD_OFF + m_] = fin ? expf(lse_old - lse_new) : 0.0f;
                smf[SCB_OFF  + m_] = fin ? expf(rowM - lse_new)    : 0.0f;  // absorbs 1/sum
                out[O_ELEMS + ((size_t)batch * HQ + h) * SEQ + s] = lse_new;
            }
        }
        __syncthreads();

        // ---- GEMM2: O[64][128] = P * V via mma.m16n8k16 ----
        float oacc[8][4];
        #pragma unroll
        for (int nb = 0; nb < 8; nb++)
            #pragma unroll
            for (int c = 0; c < 4; c++) oacc[nb][c] = 0.0f;

        #pragma unroll
        for (int ks = 0; ks < 8; ks++) {
            const int kb = ks * 8;
            const uint32_t a0 = smw[PS2_OFF + qp_idx(kb + tg,     m0 + g)];
            const uint32_t a1 = smw[PS2_OFF + qp_idx(kb + tg,     m0 + g + 8)];
            const uint32_t a2 = smw[PS2_OFF + qp_idx(kb + tg + 4, m0 + g)];
            const uint32_t a3 = smw[PS2_OFF + qp_idx(kb + tg + 4, m0 + g + 8)];
            #pragma unroll
            for (int nb = 0; nb < 8; nb++) {
                const uint32_t b0 = smw[VS2_OFF + kv_idx(kb + tg,     nbase + nb * 8 + g)];
                const uint32_t b1 = smw[VS2_OFF + kv_idx(kb + tg + 4, nbase + nb * 8 + g)];
                mma16816(oacc[nb], a0, a1, a2, a3, b0, b1);
            }
        }

        // ---- online merge + writeout (float2 per row-pair fragment) ----
        const float coldA = smf[SOLD_OFF + mA], cbA = smf[SCB_OFF + mA];
        const float coldB = smf[SOLD_OFF + mB], cbB = smf[SCB_OFF + mB];
        const int sA_ = row0 + half * 64 + mA;
        const int sB_ = row0 + half * 64 + mB;
        const size_t baseA = (((size_t)batch * SEQ + sA_) * HQ + h) * HD;
        const size_t baseB = (((size_t)batch * SEQ + sB_) * HQ + h) * HD;
        #pragma unroll
        for (int nb = 0; nb < 8; nb++) {
            const int d0 = nbase + nb * 8 + 2 * tg;
            const float2 ooA = *(const float2*)(go + baseA + d0);
            const float2 ooB = *(const float2*)(go + baseB + d0);
            float2 wA, wB;
            wA.x = coldA * ooA.x + cbA * oacc[nb][0];
            wA.y = coldA * ooA.y + cbA * oacc[nb][1];
            wB.x = coldB * ooB.x + cbB * oacc[nb][2];
            wB.y = coldB * ooB.y + cbB * oacc[nb][3];
            *(float2*)(out + baseA + d0) = wA;
            *(float2*)(out + baseB + d0) = wB;
        }
    }

    // ---------------- dynamic copy of the remaining output regions ----------------
    while (true) {
        if (t == 0) s_chunk = atomicAdd(&g_chunk_counter, 1);
        __syncthreads();
        const int c = s_chunk;
        __syncthreads();
        if (c >= nChunkTotal) break;
        copy_chunk(cc, c, t);
    }
}

extern "C" void kernel_launch(void* const* d_in, const int* in_sizes, int n_in,
                              void* d_out, int out_size)
{
    const float* q    = (const float*)d_in[0];
    const float* k    = (const float*)d_in[1];
    const float* v    = (const float*)d_in[2];
    const float* go   = (const float*)d_in[3];
    const float* glse = (const float*)d_in[4];
    const float* gq   = (const float*)d_in[5];
    const float* gk   = (const float*)d_in[6];
    const int*   biq  = (const int*)d_in[7];
    const int*   bikv = (const int*)d_in[8];
    float* out = (float*)d_out;

    const int B = in_sizes[0] / (BQ * HQ * HD);                 // 4
    const int nCompute    = B * HQ * 2;                         // 256
    const int nChunkO     = (B * (SEQ - BQ)) / ROWS_PER_CHUNK;  // 1984
    const int nChunkTotal = nChunkO + B * HQ;                   // +128 lse chunks

    const size_t smem = SMEM_WORDS * sizeof(uint32_t);          // ~83.5 KB
    cudaFuncSetAttribute(oswa_fused_kernel,
                         cudaFuncAttributeMaxDynamicSharedMemorySize, (int)smem);

    const int grid = nCompute + 40;   // 296 = 2 CTAs/SM * 148 SMs

    init_counter_kernel<<<1, 1>>>();
    oswa_fused_kernel<<<grid, 256, smem>>>(q, k, v, go, glse, gq, gk, biq, bikv,
                                           out, B, nCompute, nChunkO, nChunkTotal);
}